// round 4
// baseline (speedup 1.0000x reference)
#include <cuda_runtime.h>
#include <cstdint>

// StructureTensorEffect, B=4, C=3, H=W=1024.
// Separable form: s_u = Gx*Sy, s_v = Sx*Gy with per-batch-constant fractional
// stencils. sigma in [0.5,2.5) => JP = floor(sigma) in {0,1,2}, JM = -JP-1.
// Templated on JP so all stencil offsets are compile-time constants.
//
// Phase 1 (vertical): per-thread float4 column strip, rolling register window
//   over gmem rows -> vS, vG float4 -> smem (swizzled).
// Phase 2 (horizontal): each thread owns 8 contiguous pixels of one row;
//   window = 16 floats = 4 LDS.128 per array per channel, bank-conflict-free
//   via per-128B-block rotation swizzle of the float4 index.
// Border pixels (outer 3) use an exact 8-tap bilinear fallback.

#define Wd 1024
#define Hd 1024
#define TX 128
#define TY 16
#define HX 4
#define SW (TX + 2*HX)            // 136 floats per smem row (34 float4)
#define NTH 256
#define NSTRIP (SW/4)             // 34 float4 strips
#define CHUNK 8
#define NCHUNK (TY/CHUNK)         // 2
#define NVTASK (NSTRIP*NCHUNK*3)  // 204
#define HW (Hd*Wd)
#define SMEM_FLOATS (3*TY*SW)     // per array
#define SMEM_BYTES (2*SMEM_FLOATS*4)

// Swizzle on float4-index within a smem row: rotate odd 128B blocks by one
// float4. Makes both the stride-2 window loads (phase 2) and the contiguous
// strip stores (phase 1) bank-conflict-free.
__device__ __forceinline__ int swz(int f) {
    return (f & ~7) | ((f + ((f >> 3) & 1)) & 7);
}

__device__ __forceinline__ int clampi(int v, int lo, int hi) {
    return min(max(v, lo), hi);
}

// Exact per-pixel path replicating reference clip semantics (border only).
__device__ __noinline__ void exact_pixel(const float* __restrict__ xb, float s,
                                         int gx, int gy,
                                         float& A, float& Bv, float& Cv) {
    const float OU[8] = {-1.f,-1.f,-1.f, 0.f, 0.f, 1.f, 1.f, 1.f};
    const float OV[8] = {-1.f, 0.f, 1.f,-1.f, 1.f,-1.f, 0.f, 1.f};
    const float KU[8] = {-0.25f,-0.5f,-0.25f, 0.f, 0.f, 0.25f, 0.5f, 0.25f};
    const float KV[8] = {-0.25f, 0.f, 0.25f,-0.5f, 0.5f,-0.25f, 0.f, 0.25f};
    float su[3] = {0.f,0.f,0.f}, sv[3] = {0.f,0.f,0.f};
    #pragma unroll
    for (int t = 0; t < 8; ++t) {
        float px = (float)gx + OU[t] * s;
        float py = (float)gy + OV[t] * s;
        float x0f = floorf(px), y0f = floorf(py);
        float fx = px - x0f, fy = py - y0f;
        int x0 = clampi((int)x0f, 0, Wd - 1);
        int x1 = min(x0 + 1, Wd - 1);
        int y0 = clampi((int)y0f, 0, Hd - 1);
        int y1 = min(y0 + 1, Hd - 1);
        float w00 = (1.f - fx) * (1.f - fy);
        float w01 = fx * (1.f - fy);
        float w10 = (1.f - fx) * fy;
        float w11 = fx * fy;
        #pragma unroll
        for (int c = 0; c < 3; ++c) {
            const float* p = xb + (size_t)c * HW;
            float bil = w00 * __ldg(&p[y0 * Wd + x0]) + w01 * __ldg(&p[y0 * Wd + x1])
                      + w10 * __ldg(&p[y1 * Wd + x0]) + w11 * __ldg(&p[y1 * Wd + x1]);
            su[c] += KU[t] * bil;
            sv[c] += KV[t] * bil;
        }
    }
    A = 0.f; Bv = 0.f; Cv = 0.f;
    #pragma unroll
    for (int c = 0; c < 3; ++c) {
        float l = (c == 0) ? 100.f : 1.f;
        float a = su[c] * l, b = sv[c] * l;
        A += a * a; Bv += b * b; Cv += a * b;
    }
}

template<int JP>
__device__ __forceinline__ void run_tile(const float* __restrict__ xb, float s,
                                         float* __restrict__ smS,
                                         float* __restrict__ smG,
                                         float* __restrict__ out,
                                         int b, int bx0, int by0, int tid) {
    // weights: fp = s - JP in [0,1); fm = 1 - fp
    const float fp  = s - (float)JP;
    const float wp0 = 0.5f * (1.f - fp);
    const float wp1 = 0.5f * fp;
    const float wm0 = wp1;            // 0.5*(1-fm)
    const float wm1 = wp0;            // 0.5*fm

    // ---------------- Phase 1: vertical stencil -> smem ----------------
    if (tid < NVTASK) {
        const int c     = tid / (NSTRIP * NCHUNK);
        const int rem   = tid - c * (NSTRIP * NCHUNK);
        const int chunk = rem / NSTRIP;
        const int strip = rem - chunk * NSTRIP;

        const float* plane = xb + (size_t)c * HW;
        int gx0 = bx0 - HX + strip * 4;
        gx0 = clampi(gx0, 0, Wd - 4);

        const int ybase = by0 + chunk * CHUNK;
        const int fsw   = swz(strip) * 4;   // swizzled float offset in row

        constexpr int WIN = 2 * JP + 3;
        float4 win[WIN];
        #pragma unroll
        for (int r = -JP - 1; r <= JP; ++r) {
            int gy = clampi(ybase + r, 0, Hd - 1);
            win[r + JP + 1] = __ldg((const float4*)(plane + (size_t)gy * Wd + gx0));
        }

        float* sSrow = smS + (size_t)(c * TY + chunk * CHUNK) * SW + fsw;
        float* sGrow = smG + (size_t)(c * TY + chunk * CHUNK) * SW + fsw;

        #pragma unroll
        for (int j = 0; j < CHUNK; ++j) {
            int gy = clampi(ybase + j + JP + 1, 0, Hd - 1);
            win[(j + 2 * JP + 2) % WIN] = __ldg((const float4*)(plane + (size_t)gy * Wd + gx0));

            float4 m0 = win[(j)              % WIN];
            float4 m1 = win[(j + 1)          % WIN];
            float4 ce = win[(j + JP + 1)     % WIN];
            float4 p0 = win[(j + 2 * JP + 1) % WIN];
            float4 p1 = win[(j + 2 * JP + 2) % WIN];

            float4 vs, vg;
            {
                float mpx = wm0 * m0.x + wm1 * m1.x;
                float mpy = wm0 * m0.y + wm1 * m1.y;
                float mpz = wm0 * m0.z + wm1 * m1.z;
                float mpw = wm0 * m0.w + wm1 * m1.w;
                float ppx = wp0 * p0.x + wp1 * p1.x;
                float ppy = wp0 * p0.y + wp1 * p1.y;
                float ppz = wp0 * p0.z + wp1 * p1.z;
                float ppw = wp0 * p0.w + wp1 * p1.w;
                vs.x = ce.x + mpx + ppx;  vg.x = ppx - mpx;
                vs.y = ce.y + mpy + ppy;  vg.y = ppy - mpy;
                vs.z = ce.z + mpz + ppz;  vg.z = ppz - mpz;
                vs.w = ce.w + mpw + ppw;  vg.w = ppw - mpw;
            }
            *(float4*)(sSrow + (size_t)j * SW) = vs;
            *(float4*)(sGrow + (size_t)j * SW) = vg;
        }
    }
    __syncthreads();

    // ---------------- Phase 2: horizontal stencil + quadratics ----------------
    // Each thread: 8 contiguous pixels of one row. 16 rows x 16 colgroups = 256.
    const int cg = tid & 15;         // col group 0..15
    const int r  = tid >> 4;         // row 0..15
    const int xl = cg * 8;           // local output col (window base = xl)

    // Swizzled float offsets of the 4 window float4s (f = cg*2 + k).
    int fo[4];
    #pragma unroll
    for (int k = 0; k < 4; ++k) fo[k] = swz(cg * 2 + k) * 4;

    float accA[8], accB[8], accC[8];
    #pragma unroll
    for (int i = 0; i < 8; ++i) { accA[i] = 0.f; accB[i] = 0.f; accC[i] = 0.f; }

    constexpr int dM = 3 - JP;   // JM + 4
    constexpr int dP = 4 + JP;

    #pragma unroll
    for (int c = 0; c < 3; ++c) {
        const float l = (c == 0) ? 100.f : 1.f;
        const float* Srow = smS + (size_t)(c * TY + r) * SW;
        const float* Grow = smG + (size_t)(c * TY + r) * SW;
        float4 a0 = *(const float4*)(Srow + fo[0]);
        float4 a1 = *(const float4*)(Srow + fo[1]);
        float4 a2 = *(const float4*)(Srow + fo[2]);
        float4 a3 = *(const float4*)(Srow + fo[3]);
        float4 b0 = *(const float4*)(Grow + fo[0]);
        float4 b1 = *(const float4*)(Grow + fo[1]);
        float4 b2 = *(const float4*)(Grow + fo[2]);
        float4 b3 = *(const float4*)(Grow + fo[3]);
        float sw[16] = {a0.x,a0.y,a0.z,a0.w, a1.x,a1.y,a1.z,a1.w,
                        a2.x,a2.y,a2.z,a2.w, a3.x,a3.y,a3.z,a3.w};
        float gw[16] = {b0.x,b0.y,b0.z,b0.w, b1.x,b1.y,b1.z,b1.w,
                        b2.x,b2.y,b2.z,b2.w, b3.x,b3.y,b3.z,b3.w};
        #pragma unroll
        for (int i = 0; i < 8; ++i) {
            float su = wp0 * sw[i + dP] + wp1 * sw[i + dP + 1]
                     - wm0 * sw[i + dM] - wm1 * sw[i + dM + 1];
            float sv = gw[i + 4]
                     + wm0 * gw[i + dM] + wm1 * gw[i + dM + 1]
                     + wp0 * gw[i + dP] + wp1 * gw[i + dP + 1];
            float a  = l * su;
            float bq = l * sv;
            accA[i] += a * a;
            accB[i] += bq * bq;
            accC[i] += a * bq;
        }
    }

    // ---------------- Output ----------------
    float* out0 = out + ((size_t)b * 3 + 0) * HW;
    float* out1 = out + ((size_t)b * 3 + 1) * HW;
    float* out2 = out + ((size_t)b * 3 + 2) * HW;
    const int gxg = bx0 + xl;
    const int gy  = by0 + r;
    const bool xint = (gxg >= 3) && (gxg + 7 <= Wd - 4);
    const bool yint = (gy >= 3) && (gy <= Hd - 4);
    const size_t o = (size_t)gy * Wd + gxg;

    if (xint && yint) {
        *(float4*)(out0 + o)     = make_float4(accA[0], accA[1], accA[2], accA[3]);
        *(float4*)(out0 + o + 4) = make_float4(accA[4], accA[5], accA[6], accA[7]);
        *(float4*)(out1 + o)     = make_float4(accB[0], accB[1], accB[2], accB[3]);
        *(float4*)(out1 + o + 4) = make_float4(accB[4], accB[5], accB[6], accB[7]);
        *(float4*)(out2 + o)     = make_float4(accC[0], accC[1], accC[2], accC[3]);
        *(float4*)(out2 + o + 4) = make_float4(accC[4], accC[5], accC[6], accC[7]);
    } else {
        #pragma unroll
        for (int i = 0; i < 8; ++i) {
            int gx = gxg + i;
            float A = accA[i], Bv = accB[i], Cv = accC[i];
            if (!(yint && gx >= 3 && gx <= Wd - 4)) {
                exact_pixel(xb, s, gx, gy, A, Bv, Cv);
            }
            out0[o + i] = A;
            out1[o + i] = Bv;
            out2[o + i] = Cv;
        }
    }
}

__global__ __launch_bounds__(NTH, 4)
void st4_kernel(const float* __restrict__ x, const float* __restrict__ sigma,
                float* __restrict__ out) {
    extern __shared__ float sm[];
    float* smS = sm;
    float* smG = sm + SMEM_FLOATS;

    const int b   = blockIdx.z;
    const int bx0 = blockIdx.x * TX;
    const int by0 = blockIdx.y * TY;
    const int tid = threadIdx.x;

    const float s = __ldg(&sigma[b]);
    const int jp = clampi((int)floorf(s), 0, 2);
    const float* xb = x + (size_t)b * 3 * HW;

    if (jp == 0)      run_tile<0>(xb, s, smS, smG, out, b, bx0, by0, tid);
    else if (jp == 1) run_tile<1>(xb, s, smS, smG, out, b, bx0, by0, tid);
    else              run_tile<2>(xb, s, smS, smG, out, b, bx0, by0, tid);
}

extern "C" void kernel_launch(void* const* d_in, const int* in_sizes, int n_in,
                              void* d_out, int out_size) {
    const float* x     = (const float*)d_in[0];
    const float* sigma = (const float*)d_in[1];
    float* out = (float*)d_out;
    int B = in_sizes[1];

    static_assert(SMEM_BYTES == 52224, "smem size");
    cudaFuncSetAttribute(st4_kernel, cudaFuncAttributeMaxDynamicSharedMemorySize, SMEM_BYTES);

    dim3 grid(Wd / TX, Hd / TY, B);
    st4_kernel<<<grid, NTH, SMEM_BYTES>>>(x, sigma, out);
}

// round 5
// speedup vs baseline: 1.4594x; 1.4594x over previous
#include <cuda_runtime.h>
#include <cstdint>

// StructureTensorEffect, B=4, C=3, H=W=1024.
// Separable form: s_u = Gx*Sy, s_v = Sx*Gy with per-batch-constant fractional
// stencils. sigma in [0.5,2.5) => JP = floor(sigma) in {0,1,2}, JM = -JP-1.
// Templated on JP so all stencil offsets are compile-time constants.
//
// Phase 1 (vertical): per-thread float4 column strip, rolling register window
//   over gmem rows -> vS, vG float4 -> smem (swizzled).
// Phase 2 (horizontal): each thread owns 8 contiguous pixels of one row;
//   window = 16 floats = 4 LDS.128 per array per channel, bank-conflict-free
//   via per-128B-block rotation swizzle of the float4 index.
// Border pixels (outer 3) use an exact 8-tap bilinear fallback.
//
// R5 = R4 with occupancy 3 (R4's forced 64-reg cap caused spills).

#define Wd 1024
#define Hd 1024
#define TX 128
#define TY 16
#define HX 4
#define SW (TX + 2*HX)            // 136 floats per smem row (34 float4)
#define NTH 256
#define NSTRIP (SW/4)             // 34 float4 strips
#define CHUNK 8
#define NCHUNK (TY/CHUNK)         // 2
#define NVTASK (NSTRIP*NCHUNK*3)  // 204
#define HW (Hd*Wd)
#define SMEM_FLOATS (3*TY*SW)     // per array
#define SMEM_BYTES (2*SMEM_FLOATS*4)

// Swizzle on float4-index within a smem row: rotate odd 128B blocks by one
// float4. Makes the stride-2 window loads (phase 2) bank-conflict-free.
__device__ __forceinline__ int swz(int f) {
    return (f & ~7) | ((f + ((f >> 3) & 1)) & 7);
}

__device__ __forceinline__ int clampi(int v, int lo, int hi) {
    return min(max(v, lo), hi);
}

// Exact per-pixel path replicating reference clip semantics (border only).
__device__ __noinline__ void exact_pixel(const float* __restrict__ xb, float s,
                                         int gx, int gy,
                                         float& A, float& Bv, float& Cv) {
    const float OU[8] = {-1.f,-1.f,-1.f, 0.f, 0.f, 1.f, 1.f, 1.f};
    const float OV[8] = {-1.f, 0.f, 1.f,-1.f, 1.f,-1.f, 0.f, 1.f};
    const float KU[8] = {-0.25f,-0.5f,-0.25f, 0.f, 0.f, 0.25f, 0.5f, 0.25f};
    const float KV[8] = {-0.25f, 0.f, 0.25f,-0.5f, 0.5f,-0.25f, 0.f, 0.25f};
    float su[3] = {0.f,0.f,0.f}, sv[3] = {0.f,0.f,0.f};
    #pragma unroll
    for (int t = 0; t < 8; ++t) {
        float px = (float)gx + OU[t] * s;
        float py = (float)gy + OV[t] * s;
        float x0f = floorf(px), y0f = floorf(py);
        float fx = px - x0f, fy = py - y0f;
        int x0 = clampi((int)x0f, 0, Wd - 1);
        int x1 = min(x0 + 1, Wd - 1);
        int y0 = clampi((int)y0f, 0, Hd - 1);
        int y1 = min(y0 + 1, Hd - 1);
        float w00 = (1.f - fx) * (1.f - fy);
        float w01 = fx * (1.f - fy);
        float w10 = (1.f - fx) * fy;
        float w11 = fx * fy;
        #pragma unroll
        for (int c = 0; c < 3; ++c) {
            const float* p = xb + (size_t)c * HW;
            float bil = w00 * __ldg(&p[y0 * Wd + x0]) + w01 * __ldg(&p[y0 * Wd + x1])
                      + w10 * __ldg(&p[y1 * Wd + x0]) + w11 * __ldg(&p[y1 * Wd + x1]);
            su[c] += KU[t] * bil;
            sv[c] += KV[t] * bil;
        }
    }
    A = 0.f; Bv = 0.f; Cv = 0.f;
    #pragma unroll
    for (int c = 0; c < 3; ++c) {
        float l = (c == 0) ? 100.f : 1.f;
        float a = su[c] * l, b = sv[c] * l;
        A += a * a; Bv += b * b; Cv += a * b;
    }
}

template<int JP>
__device__ __forceinline__ void run_tile(const float* __restrict__ xb, float s,
                                         float* __restrict__ smS,
                                         float* __restrict__ smG,
                                         float* __restrict__ out,
                                         int b, int bx0, int by0, int tid) {
    // weights: fp = s - JP in [0,1); fm = 1 - fp
    const float fp  = s - (float)JP;
    const float wp0 = 0.5f * (1.f - fp);
    const float wp1 = 0.5f * fp;
    const float wm0 = wp1;            // 0.5*(1-fm)
    const float wm1 = wp0;            // 0.5*fm

    // ---------------- Phase 1: vertical stencil -> smem ----------------
    if (tid < NVTASK) {
        const int c     = tid / (NSTRIP * NCHUNK);
        const int rem   = tid - c * (NSTRIP * NCHUNK);
        const int chunk = rem / NSTRIP;
        const int strip = rem - chunk * NSTRIP;

        const float* plane = xb + (size_t)c * HW;
        int gx0 = bx0 - HX + strip * 4;
        gx0 = clampi(gx0, 0, Wd - 4);

        const int ybase = by0 + chunk * CHUNK;
        const int fsw   = swz(strip) * 4;   // swizzled float offset in row

        constexpr int WIN = 2 * JP + 3;
        float4 win[WIN];
        #pragma unroll
        for (int r = -JP - 1; r <= JP; ++r) {
            int gy = clampi(ybase + r, 0, Hd - 1);
            win[r + JP + 1] = __ldg((const float4*)(plane + (size_t)gy * Wd + gx0));
        }

        float* sSrow = smS + (size_t)(c * TY + chunk * CHUNK) * SW + fsw;
        float* sGrow = smG + (size_t)(c * TY + chunk * CHUNK) * SW + fsw;

        #pragma unroll
        for (int j = 0; j < CHUNK; ++j) {
            int gy = clampi(ybase + j + JP + 1, 0, Hd - 1);
            win[(j + 2 * JP + 2) % WIN] = __ldg((const float4*)(plane + (size_t)gy * Wd + gx0));

            float4 m0 = win[(j)              % WIN];
            float4 m1 = win[(j + 1)          % WIN];
            float4 ce = win[(j + JP + 1)     % WIN];
            float4 p0 = win[(j + 2 * JP + 1) % WIN];
            float4 p1 = win[(j + 2 * JP + 2) % WIN];

            float4 vs, vg;
            {
                float mpx = wm0 * m0.x + wm1 * m1.x;
                float mpy = wm0 * m0.y + wm1 * m1.y;
                float mpz = wm0 * m0.z + wm1 * m1.z;
                float mpw = wm0 * m0.w + wm1 * m1.w;
                float ppx = wp0 * p0.x + wp1 * p1.x;
                float ppy = wp0 * p0.y + wp1 * p1.y;
                float ppz = wp0 * p0.z + wp1 * p1.z;
                float ppw = wp0 * p0.w + wp1 * p1.w;
                vs.x = ce.x + mpx + ppx;  vg.x = ppx - mpx;
                vs.y = ce.y + mpy + ppy;  vg.y = ppy - mpy;
                vs.z = ce.z + mpz + ppz;  vg.z = ppz - mpz;
                vs.w = ce.w + mpw + ppw;  vg.w = ppw - mpw;
            }
            *(float4*)(sSrow + (size_t)j * SW) = vs;
            *(float4*)(sGrow + (size_t)j * SW) = vg;
        }
    }
    __syncthreads();

    // ---------------- Phase 2: horizontal stencil + quadratics ----------------
    // Each thread: 8 contiguous pixels of one row. 16 rows x 16 colgroups = 256.
    const int cg = tid & 15;         // col group 0..15
    const int r  = tid >> 4;         // row 0..15
    const int xl = cg * 8;           // local output col (window base = xl)

    // Swizzled float offsets of the 4 window float4s (f = cg*2 + k).
    int fo[4];
    #pragma unroll
    for (int k = 0; k < 4; ++k) fo[k] = swz(cg * 2 + k) * 4;

    float accA[8], accB[8], accC[8];
    #pragma unroll
    for (int i = 0; i < 8; ++i) { accA[i] = 0.f; accB[i] = 0.f; accC[i] = 0.f; }

    constexpr int dM = 3 - JP;   // JM + 4
    constexpr int dP = 4 + JP;

    #pragma unroll
    for (int c = 0; c < 3; ++c) {
        const float l = (c == 0) ? 100.f : 1.f;
        const float* Srow = smS + (size_t)(c * TY + r) * SW;
        const float* Grow = smG + (size_t)(c * TY + r) * SW;
        float4 a0 = *(const float4*)(Srow + fo[0]);
        float4 a1 = *(const float4*)(Srow + fo[1]);
        float4 a2 = *(const float4*)(Srow + fo[2]);
        float4 a3 = *(const float4*)(Srow + fo[3]);
        float4 b0 = *(const float4*)(Grow + fo[0]);
        float4 b1 = *(const float4*)(Grow + fo[1]);
        float4 b2 = *(const float4*)(Grow + fo[2]);
        float4 b3 = *(const float4*)(Grow + fo[3]);
        float sw[16] = {a0.x,a0.y,a0.z,a0.w, a1.x,a1.y,a1.z,a1.w,
                        a2.x,a2.y,a2.z,a2.w, a3.x,a3.y,a3.z,a3.w};
        float gw[16] = {b0.x,b0.y,b0.z,b0.w, b1.x,b1.y,b1.z,b1.w,
                        b2.x,b2.y,b2.z,b2.w, b3.x,b3.y,b3.z,b3.w};
        #pragma unroll
        for (int i = 0; i < 8; ++i) {
            float su = wp0 * sw[i + dP] + wp1 * sw[i + dP + 1]
                     - wm0 * sw[i + dM] - wm1 * sw[i + dM + 1];
            float sv = gw[i + 4]
                     + wm0 * gw[i + dM] + wm1 * gw[i + dM + 1]
                     + wp0 * gw[i + dP] + wp1 * gw[i + dP + 1];
            float a  = l * su;
            float bq = l * sv;
            accA[i] += a * a;
            accB[i] += bq * bq;
            accC[i] += a * bq;
        }
    }

    // ---------------- Output ----------------
    float* out0 = out + ((size_t)b * 3 + 0) * HW;
    float* out1 = out + ((size_t)b * 3 + 1) * HW;
    float* out2 = out + ((size_t)b * 3 + 2) * HW;
    const int gxg = bx0 + xl;
    const int gy  = by0 + r;
    const bool xint = (gxg >= 3) && (gxg + 7 <= Wd - 4);
    const bool yint = (gy >= 3) && (gy <= Hd - 4);
    const size_t o = (size_t)gy * Wd + gxg;

    if (xint && yint) {
        *(float4*)(out0 + o)     = make_float4(accA[0], accA[1], accA[2], accA[3]);
        *(float4*)(out0 + o + 4) = make_float4(accA[4], accA[5], accA[6], accA[7]);
        *(float4*)(out1 + o)     = make_float4(accB[0], accB[1], accB[2], accB[3]);
        *(float4*)(out1 + o + 4) = make_float4(accB[4], accB[5], accB[6], accB[7]);
        *(float4*)(out2 + o)     = make_float4(accC[0], accC[1], accC[2], accC[3]);
        *(float4*)(out2 + o + 4) = make_float4(accC[4], accC[5], accC[6], accC[7]);
    } else {
        #pragma unroll
        for (int i = 0; i < 8; ++i) {
            int gx = gxg + i;
            float A = accA[i], Bv = accB[i], Cv = accC[i];
            if (!(yint && gx >= 3 && gx <= Wd - 4)) {
                exact_pixel(xb, s, gx, gy, A, Bv, Cv);
            }
            out0[o + i] = A;
            out1[o + i] = Bv;
            out2[o + i] = Cv;
        }
    }
}

__global__ __launch_bounds__(NTH, 3)
void st5_kernel(const float* __restrict__ x, const float* __restrict__ sigma,
                float* __restrict__ out) {
    extern __shared__ float sm[];
    float* smS = sm;
    float* smG = sm + SMEM_FLOATS;

    const int b   = blockIdx.z;
    const int bx0 = blockIdx.x * TX;
    const int by0 = blockIdx.y * TY;
    const int tid = threadIdx.x;

    const float s = __ldg(&sigma[b]);
    const int jp = clampi((int)floorf(s), 0, 2);
    const float* xb = x + (size_t)b * 3 * HW;

    if (jp == 0)      run_tile<0>(xb, s, smS, smG, out, b, bx0, by0, tid);
    else if (jp == 1) run_tile<1>(xb, s, smS, smG, out, b, bx0, by0, tid);
    else              run_tile<2>(xb, s, smS, smG, out, b, bx0, by0, tid);
}

extern "C" void kernel_launch(void* const* d_in, const int* in_sizes, int n_in,
                              void* d_out, int out_size) {
    const float* x     = (const float*)d_in[0];
    const float* sigma = (const float*)d_in[1];
    float* out = (float*)d_out;
    int B = in_sizes[1];

    static_assert(SMEM_BYTES == 52224, "smem size");
    cudaFuncSetAttribute(st5_kernel, cudaFuncAttributeMaxDynamicSharedMemorySize, SMEM_BYTES);

    dim3 grid(Wd / TX, Hd / TY, B);
    st5_kernel<<<grid, NTH, SMEM_BYTES>>>(x, sigma, out);
}